// round 4
// baseline (speedup 1.0000x reference)
#include <cuda_runtime.h>
#include <cuda_fp16.h>

#define MAXN 200000
#define PAD  128

// Scratch (device globals — no runtime allocation allowed)
__device__ int    g_cursor[MAXN];        // fill cursors; cnt = cursor[i]-i*PAD
__device__ int    g_csr[MAXN * PAD];     // src indices binned by dst
__device__ float  g_dinv[MAXN];
__device__ __half g_hs1h[MAXN * 16];     // layer-1 scaled features (fp16)
__device__ __half g_hs2h[MAXN * 16];     // layer-2 scaled features (fp16)

// ---------------------------------------------------------------------------
__global__ void k_initcur(int n) {
    int i = blockIdx.x * blockDim.x + threadIdx.x;
    if (i < n) g_cursor[i] = i * PAD;
}

__global__ void k_fill(const int* __restrict__ src, const int* __restrict__ dst, int E) {
    int e = blockIdx.x * blockDim.x + threadIdx.x;
    if (e >= E) return;
    int d = dst[e];
    int pos = atomicAdd(&g_cursor[d], 1);
    g_csr[pos] = src[e];
}

// ---------------------------------------------------------------------------
// GEMM1: hs1 = (x @ W1) * rsqrt(deg) -> fp16; also stores dinv.
// ---------------------------------------------------------------------------
__global__ void k_gemm1(const float* __restrict__ x, const float* __restrict__ W1, int n) {
    __shared__ float xs[64 * 132];
    __shared__ float Ws[128 * 16];
    int t = threadIdx.x;
    int node0 = blockIdx.x * 64;

    for (int i = t; i < 128 * 16; i += 256) Ws[i] = W1[i];
    for (int i = t; i < 64 * 128; i += 256) {
        int node = i >> 7, k = i & 127;
        int gn = node0 + node;
        xs[node * 132 + k] = (gn < n) ? x[(size_t)gn * 128 + k] : 0.f;
    }
    __syncthreads();

    int node = t >> 2;
    int c4   = t & 3;
    int gn = node0 + node;
    if (gn >= n) return;

    const float4* xs4 = (const float4*)(xs + node * 132);
    const float4* Ws4 = (const float4*)Ws;
    float4 acc = make_float4(0.f, 0.f, 0.f, 0.f);
#pragma unroll
    for (int k4 = 0; k4 < 32; k4++) {
        float4 xv = xs4[k4];
        float4 w;
        w = Ws4[(4 * k4 + 0) * 4 + c4];
        acc.x += xv.x * w.x; acc.y += xv.x * w.y; acc.z += xv.x * w.z; acc.w += xv.x * w.w;
        w = Ws4[(4 * k4 + 1) * 4 + c4];
        acc.x += xv.y * w.x; acc.y += xv.y * w.y; acc.z += xv.y * w.z; acc.w += xv.y * w.w;
        w = Ws4[(4 * k4 + 2) * 4 + c4];
        acc.x += xv.z * w.x; acc.y += xv.z * w.y; acc.z += xv.z * w.z; acc.w += xv.z * w.w;
        w = Ws4[(4 * k4 + 3) * 4 + c4];
        acc.x += xv.w * w.x; acc.y += xv.w * w.y; acc.z += xv.w * w.z; acc.w += xv.w * w.w;
    }
    float di = rsqrtf((float)(g_cursor[gn] - gn * PAD) + 1.0f);
    if (c4 == 0) g_dinv[gn] = di;
    acc.x *= di; acc.y *= di; acc.z *= di; acc.w *= di;

    __half2* o = (__half2*)(g_hs1h + gn * 16);
    o[c4 * 2 + 0] = __float22half2_rn(make_float2(acc.x, acc.y));
    o[c4 * 2 + 1] = __float22half2_rn(make_float2(acc.z, acc.w));
}

// ---------------------------------------------------------------------------
// Warp-per-node gather core: returns t-value for channel kk = lane&15 via
// (ax,ay) totals on lanes 0..7. Lanes: sub = lane&7 (channel pair),
// jslot = lane>>3 (4-way edge parallelism). Index reads staged 32-wide.
// ---------------------------------------------------------------------------
__device__ __forceinline__ float gather_tval(const unsigned* hs, int node, int lane) {
    int sub = lane & 7;
    int jslot = lane >> 3;
    int row = node * PAD;
    int cnt = g_cursor[node] - row;
    const int* cs = g_csr + row;

    float ax = 0.f, ay = 0.f;
    for (int jb = 0; jb < cnt; jb += 32) {
        int jj = jb + lane;
        int my = (jj < cnt) ? __ldg(cs + jj) : 0;
        int steps = cnt - jb; if (steps > 32) steps = 32;
        for (int t4 = 0; t4 < steps; t4 += 4) {
            int tt = t4 + jslot;
            int s = __shfl_sync(0xffffffffu, my, tt & 31);
            if (tt < steps) {
                unsigned u = __ldg(hs + s * 8 + sub);
                float2 f = __half22float2(*(const __half2*)&u);
                ax += f.x; ay += f.y;
            }
        }
    }
    ax += __shfl_down_sync(0xffffffffu, ax, 16);
    ay += __shfl_down_sync(0xffffffffu, ay, 16);
    ax += __shfl_down_sync(0xffffffffu, ax, 8);
    ay += __shfl_down_sync(0xffffffffu, ay, 8);
    // lanes 0..7 hold totals for channels (2*sub, 2*sub+1)
    int kk = lane & 15;
    float a = __shfl_sync(0xffffffffu, ax, kk >> 1);
    float b = __shfl_sync(0xffffffffu, ay, kk >> 1);
    return (kk & 1) ? b : a;
}

// ---------------------------------------------------------------------------
// gather + combine: t1 = A~ hs1; h1 = relu(dinv*(t1+hs1)+b1);
// hs2 = (h1 @ W2)*dinv -> fp16. One warp per node, grid-strided.
// ---------------------------------------------------------------------------
__global__ void k_gather_combine(const float* __restrict__ W2,
                                 const float* __restrict__ b1, int n, int nwarps) {
    __shared__ float W2s[256];
    __shared__ float b1s[16];
    int t = threadIdx.x;
    if (t < 256) W2s[t] = W2[t];
    if (t < 16)  b1s[t] = b1[t];
    __syncthreads();

    int lane = t & 31;
    int gwarp = blockIdx.x * (blockDim.x >> 5) + (t >> 5);
    int kk = lane & 15;

    for (int node = gwarp; node < n; node += nwarps) {
        float tval = gather_tval((const unsigned*)g_hs1h, node, lane);
        float di = g_dinv[node];
        float self = __half2float(g_hs1h[node * 16 + kk]);
        float v = di * (tval + self) + b1s[kk];
        float h1v = v > 0.f ? v : 0.f;
        float acc = 0.f;
#pragma unroll
        for (int k = 0; k < 16; k++) {
            float hk = __shfl_sync(0xffffffffu, h1v, k);
            acc += hk * W2s[k * 16 + kk];
        }
        if (lane < 16) g_hs2h[node * 16 + kk] = __float2half(acc * di);
    }
}

// ---------------------------------------------------------------------------
// gather + final: t2 = A~ hs2; h2 = relu(dinv*(t2+hs2)+b2); GRU (h0=0);
// out = h' @ Wfc.T + bfc. One warp per node, grid-strided.
// ---------------------------------------------------------------------------
__device__ __forceinline__ float sigmoidf_(float x) { return 1.0f / (1.0f + expf(-x)); }

__global__ void k_gather_final(const float* __restrict__ b2,
                               const float* __restrict__ w_ih, const float* __restrict__ b_ih,
                               const float* __restrict__ b_hh,
                               const float* __restrict__ Wfc, const float* __restrict__ bfc,
                               float* __restrict__ out, int n, int nwarps) {
    __shared__ float wihs[768];
    __shared__ float wfcs[512];
    __shared__ float bihs[48];
    __shared__ float bhhs[48];
    __shared__ float bfcs[32];
    __shared__ float b2s[16];
    int t = threadIdx.x;
    for (int i = t; i < 768; i += blockDim.x) wihs[i] = w_ih[i];
    for (int i = t; i < 512; i += blockDim.x) wfcs[i] = Wfc[i];
    if (t < 48) { bihs[t] = b_ih[t]; bhhs[t] = b_hh[t]; }
    if (t < 32) bfcs[t] = bfc[t];
    if (t < 16) b2s[t] = b2[t];
    __syncthreads();

    int lane = t & 31;
    int gwarp = blockIdx.x * (blockDim.x >> 5) + (t >> 5);
    int kk = lane & 15;

    for (int node = gwarp; node < n; node += nwarps) {
        float tval = gather_tval((const unsigned*)g_hs2h, node, lane);
        float di = g_dinv[node];
        float self = __half2float(g_hs2h[node * 16 + kk]);
        float v = di * (tval + self) + b2s[kk];
        float h2v = v > 0.f ? v : 0.f;

        // GRU gate k = kk (lanes 16..31 duplicate lanes 0..15)
        float ar = bihs[kk], az = bihs[16 + kk], an = bihs[32 + kk];
#pragma unroll
        for (int c = 0; c < 16; c++) {
            float hc = __shfl_sync(0xffffffffu, h2v, c);
            ar += hc * wihs[kk * 16 + c];
            az += hc * wihs[(16 + kk) * 16 + c];
            an += hc * wihs[(32 + kk) * 16 + c];
        }
        float r  = sigmoidf_(ar + bhhs[kk]);
        float z  = sigmoidf_(az + bhhs[16 + kk]);
        float nn = tanhf(an + r * bhhs[32 + kk]);
        float houtv = (1.0f - z) * nn;   // lane k holds hout[k] for k<16

        // FC: lane q (0..31) computes output channel q
        float o = bfcs[lane];
#pragma unroll
        for (int k = 0; k < 16; k++) {
            float hk = __shfl_sync(0xffffffffu, houtv, k);
            o += hk * wfcs[lane * 16 + k];
        }
        out[(size_t)node * 32 + lane] = o;
    }
}

// ---------------------------------------------------------------------------
extern "C" void kernel_launch(void* const* d_in, const int* in_sizes, int n_in,
                              void* d_out, int out_size) {
    const float* x    = (const float*)d_in[0];
    const int*   ei   = (const int*)  d_in[1];
    const float* W1   = (const float*)d_in[3];
    const float* b1   = (const float*)d_in[4];
    const float* W2   = (const float*)d_in[5];
    const float* b2   = (const float*)d_in[6];
    const float* w_ih = (const float*)d_in[7];
    const float* b_ih = (const float*)d_in[9];
    const float* b_hh = (const float*)d_in[10];
    const float* Wfc  = (const float*)d_in[11];
    const float* bfc  = (const float*)d_in[12];
    float* out = (float*)d_out;

    int n = in_sizes[2];           // N nodes
    int E = in_sizes[1] / 2;       // edges
    const int* src = ei;
    const int* dst = ei + E;

    k_initcur<<<(n + 255) / 256, 256>>>(n);
    k_fill<<<(E + 255) / 256, 256>>>(src, dst, E);
    k_gemm1<<<(n + 63) / 64, 256>>>(x, W1, n);

    int blocks = 2368;                 // 148 SMs * 16
    int nwarps = blocks * (256 / 32);
    k_gather_combine<<<blocks, 256>>>(W2, b1, n, nwarps);
    k_gather_final<<<blocks, 256>>>(b2, w_ih, b_ih, b_hh, Wfc, bfc, out, n, nwarps);
}

// round 5
// speedup vs baseline: 1.1863x; 1.1863x over previous
#include <cuda_runtime.h>
#include <cuda_fp16.h>

#define MAXN 200000
#define MAXE 6500000

// Scratch (device globals — no runtime allocation allowed)
__device__ int    g_cnt[MAXN];        // in-degree (without self loop)
__device__ int    g_rowptr[MAXN];     // CSR row start
__device__ int    g_cursor[MAXN];     // fill cursors
__device__ int    g_bsums[256];       // block sums for scan
__device__ int    g_csr[MAXE];        // src indices grouped by dst (compact)
__device__ float  g_dinv[MAXN];
__device__ __half g_hs1h[MAXN * 16];  // layer-1 scaled features (fp16)
__device__ __half g_hs2h[MAXN * 16];  // layer-2 scaled features (fp16)

// ---------------------------------------------------------------------------
__global__ void k_zero(int n) {
    int i = blockIdx.x * blockDim.x + threadIdx.x;
    if (i < n) g_cnt[i] = 0;
}

__global__ void k_count(const int* __restrict__ dst, int E) {
    int e = blockIdx.x * blockDim.x + threadIdx.x;
    if (e < E) atomicAdd(&g_cnt[dst[e]], 1);
}

// scan part 1: per-block (1024 elements) sums
__global__ void k_scan1(int n) {
    __shared__ int sh[256];
    int b = blockIdx.x, t = threadIdx.x;
    int i0 = b * 1024 + t * 4;
    int s = 0;
#pragma unroll
    for (int k = 0; k < 4; k++) { int i = i0 + k; if (i < n) s += g_cnt[i]; }
    sh[t] = s; __syncthreads();
    for (int off = 128; off > 0; off >>= 1) {
        if (t < off) sh[t] += sh[t + off];
        __syncthreads();
    }
    if (t == 0) g_bsums[b] = sh[0];
}

// scan part 2: every block redundantly scans block sums, then scans its chunk
__global__ void k_scan23(int n, int nb) {
    __shared__ int bs[256];
    __shared__ int sh[256];
    int b = blockIdx.x, t = threadIdx.x;

    int v = (t < nb) ? g_bsums[t] : 0;
    bs[t] = v; __syncthreads();
    for (int off = 1; off < 256; off <<= 1) {
        int a = (t >= off) ? bs[t - off] : 0;
        __syncthreads();
        bs[t] += a;
        __syncthreads();
    }
    int blockoff = (b > 0) ? bs[b - 1] : 0;

    int i0 = b * 1024 + t * 4;
    int c[4]; int s = 0;
#pragma unroll
    for (int k = 0; k < 4; k++) { int i = i0 + k; c[k] = (i < n) ? g_cnt[i] : 0; s += c[k]; }
    int tot = s;
    sh[t] = tot; __syncthreads();
    for (int off = 1; off < 256; off <<= 1) {
        int a = (t >= off) ? sh[t - off] : 0;
        __syncthreads();
        sh[t] += a;
        __syncthreads();
    }
    int run = sh[t] - tot + blockoff;
#pragma unroll
    for (int k = 0; k < 4; k++) {
        int i = i0 + k;
        if (i < n) { g_rowptr[i] = run; g_cursor[i] = run; run += c[k]; }
    }
}

__global__ void k_fill(const int* __restrict__ src, const int* __restrict__ dst, int E) {
    int e = blockIdx.x * blockDim.x + threadIdx.x;
    if (e >= E) return;
    int d = dst[e];
    int pos = atomicAdd(&g_cursor[d], 1);
    g_csr[pos] = src[e];
}

// ---------------------------------------------------------------------------
// GEMM1: hs1 = (x @ W1) * rsqrt(deg) -> fp16; also stores dinv.
// ---------------------------------------------------------------------------
__global__ void k_gemm1(const float* __restrict__ x, const float* __restrict__ W1, int n) {
    __shared__ float xs[64 * 132];
    __shared__ float Ws[128 * 16];
    int t = threadIdx.x;
    int node0 = blockIdx.x * 64;

    for (int i = t; i < 128 * 16; i += 256) Ws[i] = W1[i];
    for (int i = t; i < 64 * 128; i += 256) {
        int node = i >> 7, k = i & 127;
        int gn = node0 + node;
        xs[node * 132 + k] = (gn < n) ? x[(size_t)gn * 128 + k] : 0.f;
    }
    __syncthreads();

    int node = t >> 2;
    int c4   = t & 3;
    int gn = node0 + node;
    if (gn >= n) return;

    const float4* xs4 = (const float4*)(xs + node * 132);
    const float4* Ws4 = (const float4*)Ws;
    float4 acc = make_float4(0.f, 0.f, 0.f, 0.f);
#pragma unroll
    for (int k4 = 0; k4 < 32; k4++) {
        float4 xv = xs4[k4];
        float4 w;
        w = Ws4[(4 * k4 + 0) * 4 + c4];
        acc.x += xv.x * w.x; acc.y += xv.x * w.y; acc.z += xv.x * w.z; acc.w += xv.x * w.w;
        w = Ws4[(4 * k4 + 1) * 4 + c4];
        acc.x += xv.y * w.x; acc.y += xv.y * w.y; acc.z += xv.y * w.z; acc.w += xv.y * w.w;
        w = Ws4[(4 * k4 + 2) * 4 + c4];
        acc.x += xv.z * w.x; acc.y += xv.z * w.y; acc.z += xv.z * w.z; acc.w += xv.z * w.w;
        w = Ws4[(4 * k4 + 3) * 4 + c4];
        acc.x += xv.w * w.x; acc.y += xv.w * w.y; acc.z += xv.w * w.z; acc.w += xv.w * w.w;
    }
    float di = rsqrtf((float)g_cnt[gn] + 1.0f);
    if (c4 == 0) g_dinv[gn] = di;
    acc.x *= di; acc.y *= di; acc.z *= di; acc.w *= di;

    __half2* o = (__half2*)(g_hs1h + gn * 16);
    o[c4 * 2 + 0] = __float22half2_rn(make_float2(acc.x, acc.y));
    o[c4 * 2 + 1] = __float22half2_rn(make_float2(acc.z, acc.w));
}

// ---------------------------------------------------------------------------
// Gather core: 4 threads per node (quad). Thread sub owns channels
// 4*sub..4*sub+3 (one uint2 = 4 halves per edge). Returns 4 fp32 sums.
// ---------------------------------------------------------------------------
__device__ __forceinline__ void gather4(const uint2* __restrict__ hs, int node, int sub,
                                        float& a0, float& a1, float& a2, float& a3) {
    int row = g_rowptr[node];
    int cnt = g_cnt[node];
    const int* cs = g_csr + row;
    a0 = a1 = a2 = a3 = 0.f;

    int j = 0;
    for (; j + 4 <= cnt; j += 4) {
        int s0 = __ldg(cs + j + 0);
        int s1 = __ldg(cs + j + 1);
        int s2 = __ldg(cs + j + 2);
        int s3 = __ldg(cs + j + 3);
        uint2 u0 = __ldg(hs + s0 * 4 + sub);
        uint2 u1 = __ldg(hs + s1 * 4 + sub);
        uint2 u2 = __ldg(hs + s2 * 4 + sub);
        uint2 u3 = __ldg(hs + s3 * 4 + sub);
        float2 f, g;
        f = __half22float2(*(const __half2*)&u0.x); g = __half22float2(*(const __half2*)&u0.y);
        a0 += f.x; a1 += f.y; a2 += g.x; a3 += g.y;
        f = __half22float2(*(const __half2*)&u1.x); g = __half22float2(*(const __half2*)&u1.y);
        a0 += f.x; a1 += f.y; a2 += g.x; a3 += g.y;
        f = __half22float2(*(const __half2*)&u2.x); g = __half22float2(*(const __half2*)&u2.y);
        a0 += f.x; a1 += f.y; a2 += g.x; a3 += g.y;
        f = __half22float2(*(const __half2*)&u3.x); g = __half22float2(*(const __half2*)&u3.y);
        a0 += f.x; a1 += f.y; a2 += g.x; a3 += g.y;
    }
    for (; j < cnt; j++) {
        int s = __ldg(cs + j);
        uint2 u = __ldg(hs + s * 4 + sub);
        float2 f = __half22float2(*(const __half2*)&u.x);
        float2 g = __half22float2(*(const __half2*)&u.y);
        a0 += f.x; a1 += f.y; a2 += g.x; a3 += g.y;
    }
}

// ---------------------------------------------------------------------------
// gather + combine: h1 = relu(dinv*(t1+self)+b1); hs2 = (h1 @ W2)*dinv -> fp16
// ---------------------------------------------------------------------------
__global__ void k_gatherC(const float* __restrict__ W2, const float* __restrict__ b1, int n) {
    __shared__ float W2s[256];
    __shared__ float b1s[16];
    int t = threadIdx.x;
    if (t < 256) W2s[t] = W2[t];
    if (t < 16)  b1s[t] = b1[t];
    __syncthreads();

    int gid = blockIdx.x * blockDim.x + t;
    int node = gid >> 2;
    int sub  = gid & 3;
    if (node >= n) return;
    int lane = t & 31;
    int lbase = lane & ~3;

    float a0, a1, a2, a3;
    gather4((const uint2*)g_hs1h, node, sub, a0, a1, a2, a3);

    float di = g_dinv[node];
    uint2 su = __ldg((const uint2*)g_hs1h + node * 4 + sub);
    float2 f = __half22float2(*(const __half2*)&su.x);
    float2 g = __half22float2(*(const __half2*)&su.y);
    float r0 = di * (a0 + f.x) + b1s[sub * 4 + 0]; r0 = r0 > 0.f ? r0 : 0.f;
    float r1 = di * (a1 + f.y) + b1s[sub * 4 + 1]; r1 = r1 > 0.f ? r1 : 0.f;
    float r2 = di * (a2 + g.x) + b1s[sub * 4 + 2]; r2 = r2 > 0.f ? r2 : 0.f;
    float r3 = di * (a3 + g.y) + b1s[sub * 4 + 3]; r3 = r3 > 0.f ? r3 : 0.f;

    // out channels c = 4*sub..4*sub+3 : o_c = sum_k h1[k] * W2[k][c]
    float o0 = 0.f, o1 = 0.f, o2 = 0.f, o3 = 0.f;
#pragma unroll
    for (int kq = 0; kq < 4; kq++) {
        float h0 = __shfl_sync(0xffffffffu, r0, lbase + kq);
        float h1 = __shfl_sync(0xffffffffu, r1, lbase + kq);
        float h2 = __shfl_sync(0xffffffffu, r2, lbase + kq);
        float h3 = __shfl_sync(0xffffffffu, r3, lbase + kq);
        const float* w0 = W2s + (kq * 4 + 0) * 16 + sub * 4;
        const float* w1 = W2s + (kq * 4 + 1) * 16 + sub * 4;
        const float* w2 = W2s + (kq * 4 + 2) * 16 + sub * 4;
        const float* w3 = W2s + (kq * 4 + 3) * 16 + sub * 4;
        o0 += h0 * w0[0] + h1 * w1[0] + h2 * w2[0] + h3 * w3[0];
        o1 += h0 * w0[1] + h1 * w1[1] + h2 * w2[1] + h3 * w3[1];
        o2 += h0 * w0[2] + h1 * w1[2] + h2 * w2[2] + h3 * w3[2];
        o3 += h0 * w0[3] + h1 * w1[3] + h2 * w2[3] + h3 * w3[3];
    }
    uint2 ov;
    __half2 p0 = __float22half2_rn(make_float2(o0 * di, o1 * di));
    __half2 p1 = __float22half2_rn(make_float2(o2 * di, o3 * di));
    ov.x = *(const unsigned*)&p0; ov.y = *(const unsigned*)&p1;
    ((uint2*)g_hs2h)[node * 4 + sub] = ov;
}

// ---------------------------------------------------------------------------
// gather + final: h2 = relu(dinv*(t2+self)+b2); GRU (h0=0); out = h'@Wfc.T+bfc
// ---------------------------------------------------------------------------
__device__ __forceinline__ float sigmoidf_(float x) { return 1.0f / (1.0f + expf(-x)); }

__global__ void k_gatherF(const float* __restrict__ b2,
                          const float* __restrict__ w_ih, const float* __restrict__ b_ih,
                          const float* __restrict__ b_hh,
                          const float* __restrict__ Wfc, const float* __restrict__ bfc,
                          float* __restrict__ out, int n) {
    __shared__ float wihs[768];
    __shared__ float wfcs[512];
    __shared__ float bihs[48];
    __shared__ float bhhs[48];
    __shared__ float bfcs[32];
    __shared__ float b2s[16];
    int t = threadIdx.x;
    for (int i = t; i < 768; i += blockDim.x) wihs[i] = w_ih[i];
    for (int i = t; i < 512; i += blockDim.x) wfcs[i] = Wfc[i];
    if (t < 48) { bihs[t] = b_ih[t]; bhhs[t] = b_hh[t]; }
    if (t < 32) bfcs[t] = bfc[t];
    if (t < 16) b2s[t] = b2[t];
    __syncthreads();

    int gid = blockIdx.x * blockDim.x + t;
    int node = gid >> 2;
    int sub  = gid & 3;
    if (node >= n) return;
    int lane = t & 31;
    int lbase = lane & ~3;

    float a0, a1, a2, a3;
    gather4((const uint2*)g_hs2h, node, sub, a0, a1, a2, a3);

    float di = g_dinv[node];
    uint2 su = __ldg((const uint2*)g_hs2h + node * 4 + sub);
    float2 f = __half22float2(*(const __half2*)&su.x);
    float2 g = __half22float2(*(const __half2*)&su.y);
    float r0 = di * (a0 + f.x) + b2s[sub * 4 + 0]; r0 = r0 > 0.f ? r0 : 0.f;
    float r1 = di * (a1 + f.y) + b2s[sub * 4 + 1]; r1 = r1 > 0.f ? r1 : 0.f;
    float r2 = di * (a2 + g.x) + b2s[sub * 4 + 2]; r2 = r2 > 0.f ? r2 : 0.f;
    float r3 = di * (a3 + g.y) + b2s[sub * 4 + 3]; r3 = r3 > 0.f ? r3 : 0.f;

    // GRU gates for my k's: k = 4*sub + i2
    float ar0, ar1, ar2, ar3, az0, az1, az2, az3, an0, an1, an2, an3;
    {
        int kb = sub * 4;
        ar0 = bihs[kb + 0]; ar1 = bihs[kb + 1]; ar2 = bihs[kb + 2]; ar3 = bihs[kb + 3];
        az0 = bihs[16 + kb + 0]; az1 = bihs[16 + kb + 1]; az2 = bihs[16 + kb + 2]; az3 = bihs[16 + kb + 3];
        an0 = bihs[32 + kb + 0]; an1 = bihs[32 + kb + 1]; an2 = bihs[32 + kb + 2]; an3 = bihs[32 + kb + 3];
    }
#pragma unroll
    for (int kq = 0; kq < 4; kq++) {
        float h0 = __shfl_sync(0xffffffffu, r0, lbase + kq);
        float h1 = __shfl_sync(0xffffffffu, r1, lbase + kq);
        float h2 = __shfl_sync(0xffffffffu, r2, lbase + kq);
        float h3 = __shfl_sync(0xffffffffu, r3, lbase + kq);
        float hc[4] = {h0, h1, h2, h3};
#pragma unroll
        for (int i = 0; i < 4; i++) {
            int c = kq * 4 + i;
            float hv = hc[i];
            int kb = sub * 4;
            ar0 += hv * wihs[(kb + 0) * 16 + c];
            ar1 += hv * wihs[(kb + 1) * 16 + c];
            ar2 += hv * wihs[(kb + 2) * 16 + c];
            ar3 += hv * wihs[(kb + 3) * 16 + c];
            az0 += hv * wihs[(16 + kb + 0) * 16 + c];
            az1 += hv * wihs[(16 + kb + 1) * 16 + c];
            az2 += hv * wihs[(16 + kb + 2) * 16 + c];
            az3 += hv * wihs[(16 + kb + 3) * 16 + c];
            an0 += hv * wihs[(32 + kb + 0) * 16 + c];
            an1 += hv * wihs[(32 + kb + 1) * 16 + c];
            an2 += hv * wihs[(32 + kb + 2) * 16 + c];
            an3 += hv * wihs[(32 + kb + 3) * 16 + c];
        }
    }
    int kb = sub * 4;
    float ho0, ho1, ho2, ho3;
    {
        float r, z, nn;
        r = sigmoidf_(ar0 + bhhs[kb + 0]); z = sigmoidf_(az0 + bhhs[16 + kb + 0]);
        nn = tanhf(an0 + r * bhhs[32 + kb + 0]); ho0 = (1.f - z) * nn;
        r = sigmoidf_(ar1 + bhhs[kb + 1]); z = sigmoidf_(az1 + bhhs[16 + kb + 1]);
        nn = tanhf(an1 + r * bhhs[32 + kb + 1]); ho1 = (1.f - z) * nn;
        r = sigmoidf_(ar2 + bhhs[kb + 2]); z = sigmoidf_(az2 + bhhs[16 + kb + 2]);
        nn = tanhf(an2 + r * bhhs[32 + kb + 2]); ho2 = (1.f - z) * nn;
        r = sigmoidf_(ar3 + bhhs[kb + 3]); z = sigmoidf_(az3 + bhhs[16 + kb + 3]);
        nn = tanhf(an3 + r * bhhs[32 + kb + 3]); ho3 = (1.f - z) * nn;
    }

    // FC: thread sub covers out channels 8*sub..8*sub+7
    float o[8];
#pragma unroll
    for (int q = 0; q < 8; q++) o[q] = bfcs[sub * 8 + q];
#pragma unroll
    for (int kq = 0; kq < 4; kq++) {
        float h0 = __shfl_sync(0xffffffffu, ho0, lbase + kq);
        float h1 = __shfl_sync(0xffffffffu, ho1, lbase + kq);
        float h2 = __shfl_sync(0xffffffffu, ho2, lbase + kq);
        float h3 = __shfl_sync(0xffffffffu, ho3, lbase + kq);
#pragma unroll
        for (int q = 0; q < 8; q++) {
            const float* w = wfcs + (sub * 8 + q) * 16 + kq * 4;
            o[q] += h0 * w[0] + h1 * w[1] + h2 * w[2] + h3 * w[3];
        }
    }
    float4* op = (float4*)(out + (size_t)node * 32 + sub * 8);
    op[0] = make_float4(o[0], o[1], o[2], o[3]);
    op[1] = make_float4(o[4], o[5], o[6], o[7]);
}

// ---------------------------------------------------------------------------
extern "C" void kernel_launch(void* const* d_in, const int* in_sizes, int n_in,
                              void* d_out, int out_size) {
    const float* x    = (const float*)d_in[0];
    const int*   ei   = (const int*)  d_in[1];
    const float* W1   = (const float*)d_in[3];
    const float* b1   = (const float*)d_in[4];
    const float* W2   = (const float*)d_in[5];
    const float* b2   = (const float*)d_in[6];
    const float* w_ih = (const float*)d_in[7];
    const float* b_ih = (const float*)d_in[9];
    const float* b_hh = (const float*)d_in[10];
    const float* Wfc  = (const float*)d_in[11];
    const float* bfc  = (const float*)d_in[12];
    float* out = (float*)d_out;

    int n = in_sizes[2];           // N nodes
    int E = in_sizes[1] / 2;       // edges
    const int* src = ei;
    const int* dst = ei + E;

    int nb = (n + 1023) / 1024;    // scan blocks (<=256)

    k_zero<<<(n + 255) / 256, 256>>>(n);
    k_count<<<(E + 255) / 256, 256>>>(dst, E);
    k_scan1<<<nb, 256>>>(n);
    k_gemm1<<<(n + 63) / 64, 256>>>(x, W1, n);          // profiled slot 4
    k_scan23<<<nb, 256>>>(n, nb);
    k_fill<<<(E + 255) / 256, 256>>>(src, dst, E);

    int n4 = n * 4;
    k_gatherC<<<(n4 + 255) / 256, 256>>>(W2, b1, n);
    k_gatherF<<<(n4 + 255) / 256, 256>>>(b2, w_ih, b_ih, b_hh, Wfc, bfc, out, n);
}

// round 6
// speedup vs baseline: 1.5139x; 1.2762x over previous
#include <cuda_runtime.h>
#include <cuda_fp16.h>

#define MAXN 200000
#define MAXE 6500000

// Scratch (device globals — no runtime allocation allowed)
// g_cnt is zero on first call (static init) and re-zeroed by k_final each call.
__device__ int    g_cnt[MAXN];        // in-degree (without self loop)
__device__ int    g_rowptr[MAXN];     // CSR row start
__device__ int    g_cursor[MAXN];     // fill cursors
__device__ int    g_bsums[256];       // block sums for scan
__device__ int    g_csr[MAXE];        // src indices grouped by dst (compact)
__device__ float  g_dinv[MAXN];
__device__ __half g_hs1h[MAXN * 16];  // layer-1 scaled features (fp16)
__device__ __half g_hs2h[MAXN * 16];  // layer-2 scaled features (fp16)
__device__ float4 g_t1[MAXN * 4];     // layer-1 neighbor sums (fp32)
__device__ float4 g_t2[MAXN * 4];     // layer-2 neighbor sums

// ---------------------------------------------------------------------------
__global__ void k_count(const int* __restrict__ dst, int E) {
    int e = blockIdx.x * blockDim.x + threadIdx.x;
    if (e < E) atomicAdd(&g_cnt[dst[e]], 1);
}

// scan part 1: per-block (1024 elements) sums
__global__ void k_scan1(int n) {
    __shared__ int sh[256];
    int b = blockIdx.x, t = threadIdx.x;
    int i0 = b * 1024 + t * 4;
    int s = 0;
#pragma unroll
    for (int k = 0; k < 4; k++) { int i = i0 + k; if (i < n) s += g_cnt[i]; }
    sh[t] = s; __syncthreads();
    for (int off = 128; off > 0; off >>= 1) {
        if (t < off) sh[t] += sh[t + off];
        __syncthreads();
    }
    if (t == 0) g_bsums[b] = sh[0];
}

// scan part 2: every block redundantly scans block sums, then scans its chunk
__global__ void k_scan23(int n, int nb) {
    __shared__ int bs[256];
    __shared__ int sh[256];
    int b = blockIdx.x, t = threadIdx.x;

    int v = (t < nb) ? g_bsums[t] : 0;
    bs[t] = v; __syncthreads();
    for (int off = 1; off < 256; off <<= 1) {
        int a = (t >= off) ? bs[t - off] : 0;
        __syncthreads();
        bs[t] += a;
        __syncthreads();
    }
    int blockoff = (b > 0) ? bs[b - 1] : 0;

    int i0 = b * 1024 + t * 4;
    int c[4]; int s = 0;
#pragma unroll
    for (int k = 0; k < 4; k++) { int i = i0 + k; c[k] = (i < n) ? g_cnt[i] : 0; s += c[k]; }
    int tot = s;
    sh[t] = tot; __syncthreads();
    for (int off = 1; off < 256; off <<= 1) {
        int a = (t >= off) ? sh[t - off] : 0;
        __syncthreads();
        sh[t] += a;
        __syncthreads();
    }
    int run = sh[t] - tot + blockoff;
#pragma unroll
    for (int k = 0; k < 4; k++) {
        int i = i0 + k;
        if (i < n) { g_rowptr[i] = run; g_cursor[i] = run; run += c[k]; }
    }
}

__global__ void k_fill(const int* __restrict__ src, const int* __restrict__ dst, int E) {
    int e = blockIdx.x * blockDim.x + threadIdx.x;
    if (e >= E) return;
    int d = dst[e];
    int pos = atomicAdd(&g_cursor[d], 1);
    g_csr[pos] = src[e];
}

// ---------------------------------------------------------------------------
// GEMM1: hs1 = (x @ W1) * rsqrt(deg) -> fp16; also stores dinv.
// 128 threads, 64 nodes/block. Thread: 2 nodes x 4 channels (register tile)
// -> 6 LDS.128 per 32 FMA in the inner loop.
// ---------------------------------------------------------------------------
__global__ void k_gemm1(const float* __restrict__ x, const float* __restrict__ W1, int n) {
    __shared__ float xs[64 * 132];
    __shared__ float Ws[128 * 16];
    int t = threadIdx.x;              // 128 threads
    int node0 = blockIdx.x * 64;

    {
        const float4* W4 = (const float4*)W1;
        float4* Wd = (float4*)Ws;
        for (int i = t; i < 512; i += 128) Wd[i] = W4[i];
    }
    {
        const float4* x4 = (const float4*)x;
        for (int i = t; i < 2048; i += 128) {
            int node = i >> 5;        // 32 float4 per node
            int k4 = i & 31;
            int gn = node0 + node;
            float4 v = make_float4(0.f, 0.f, 0.f, 0.f);
            if (gn < n) v = x4[(size_t)gn * 32 + k4];
            *(float4*)&xs[node * 132 + k4 * 4] = v;
        }
    }
    __syncthreads();

    int c4 = t & 3;                   // channel quad
    int g  = t >> 2;                  // 0..31 -> nodes 2g, 2g+1
    int na = node0 + g * 2;
    int nb = na + 1;

    const float4* xa4 = (const float4*)(xs + (g * 2 + 0) * 132);
    const float4* xb4 = (const float4*)(xs + (g * 2 + 1) * 132);
    const float4* Ws4 = (const float4*)Ws;
    float4 A = make_float4(0.f, 0.f, 0.f, 0.f);
    float4 B = make_float4(0.f, 0.f, 0.f, 0.f);
#pragma unroll
    for (int k4 = 0; k4 < 32; k4++) {
        float4 xa = xa4[k4];
        float4 xb = xb4[k4];
        float4 w;
        w = Ws4[(4 * k4 + 0) * 4 + c4];
        A.x += xa.x * w.x; A.y += xa.x * w.y; A.z += xa.x * w.z; A.w += xa.x * w.w;
        B.x += xb.x * w.x; B.y += xb.x * w.y; B.z += xb.x * w.z; B.w += xb.x * w.w;
        w = Ws4[(4 * k4 + 1) * 4 + c4];
        A.x += xa.y * w.x; A.y += xa.y * w.y; A.z += xa.y * w.z; A.w += xa.y * w.w;
        B.x += xb.y * w.x; B.y += xb.y * w.y; B.z += xb.y * w.z; B.w += xb.y * w.w;
        w = Ws4[(4 * k4 + 2) * 4 + c4];
        A.x += xa.z * w.x; A.y += xa.z * w.y; A.z += xa.z * w.z; A.w += xa.z * w.w;
        B.x += xb.z * w.x; B.y += xb.z * w.y; B.z += xb.z * w.z; B.w += xb.z * w.w;
        w = Ws4[(4 * k4 + 3) * 4 + c4];
        A.x += xa.w * w.x; A.y += xa.w * w.y; A.z += xa.w * w.z; A.w += xa.w * w.w;
        B.x += xb.w * w.x; B.y += xb.w * w.y; B.z += xb.w * w.z; B.w += xb.w * w.w;
    }
    if (na < n) {
        float di = rsqrtf((float)g_cnt[na] + 1.0f);
        if (c4 == 0) g_dinv[na] = di;
        __half2* o = (__half2*)(g_hs1h + na * 16);
        o[c4 * 2 + 0] = __float22half2_rn(make_float2(A.x * di, A.y * di));
        o[c4 * 2 + 1] = __float22half2_rn(make_float2(A.z * di, A.w * di));
    }
    if (nb < n) {
        float di = rsqrtf((float)g_cnt[nb] + 1.0f);
        if (c4 == 0) g_dinv[nb] = di;
        __half2* o = (__half2*)(g_hs1h + nb * 16);
        o[c4 * 2 + 0] = __float22half2_rn(make_float2(B.x * di, B.y * di));
        o[c4 * 2 + 1] = __float22half2_rn(make_float2(B.z * di, B.w * di));
    }
}

// ---------------------------------------------------------------------------
// gather pass: t[i] = sum_{j in adj(i)} hs[src_j]. 8 threads per node,
// each thread owns one half2 (2 channels). Batched 8-deep for MLP.
// ---------------------------------------------------------------------------
__global__ void k_gather(int n, int layer) {
    int gid = blockIdx.x * blockDim.x + threadIdx.x;
    int node = gid >> 3;
    int sub  = gid & 7;
    if (node >= n) return;
    const unsigned* hs = (const unsigned*)(layer ? g_hs2h : g_hs1h);
    float2* tt = (float2*)(layer ? g_t2 : g_t1);

    int row = g_rowptr[node];
    int cnt = g_cnt[node];
    const int* cs = g_csr + row;

    float ax = 0.f, ay = 0.f;
    int j = 0;
    for (; j + 8 <= cnt; j += 8) {
        int s[8];
#pragma unroll
        for (int q = 0; q < 8; q++) s[q] = __ldg(cs + j + q);
        unsigned u[8];
#pragma unroll
        for (int q = 0; q < 8; q++) u[q] = __ldg(hs + s[q] * 8 + sub);
#pragma unroll
        for (int q = 0; q < 8; q++) {
            float2 f = __half22float2(*(const __half2*)&u[q]);
            ax += f.x; ay += f.y;
        }
    }
    for (; j < cnt; j++) {
        int s = __ldg(cs + j);
        unsigned u = __ldg(hs + s * 8 + sub);
        float2 f = __half22float2(*(const __half2*)&u);
        ax += f.x; ay += f.y;
    }
    tt[node * 8 + sub] = make_float2(ax, ay);
}

// ---------------------------------------------------------------------------
// combine: h1 = relu(dinv*(t1+hs1)+b1); hs2 = (h1 @ W2)*dinv -> fp16.
// ---------------------------------------------------------------------------
__global__ void k_combine(const float* __restrict__ W2, const float* __restrict__ b1, int n) {
    __shared__ float W2s[256];
    __shared__ float b1s[16];
    int t = threadIdx.x;
    if (t < 256) W2s[t] = W2[t];
    if (t < 16)  b1s[t] = b1[t];
    __syncthreads();

    int i = blockIdx.x * blockDim.x + threadIdx.x;
    if (i >= n) return;
    float di = g_dinv[i];

    float h1[16];
#pragma unroll
    for (int q = 0; q < 4; q++) {
        float4 tv = g_t1[i * 4 + q];
        float2 s0 = __half22float2(((const __half2*)g_hs1h)[i * 8 + q * 2 + 0]);
        float2 s1 = __half22float2(((const __half2*)g_hs1h)[i * 8 + q * 2 + 1]);
        float v;
        v = di * (tv.x + s0.x) + b1s[q * 4 + 0]; h1[q * 4 + 0] = v > 0.f ? v : 0.f;
        v = di * (tv.y + s0.y) + b1s[q * 4 + 1]; h1[q * 4 + 1] = v > 0.f ? v : 0.f;
        v = di * (tv.z + s1.x) + b1s[q * 4 + 2]; h1[q * 4 + 2] = v > 0.f ? v : 0.f;
        v = di * (tv.w + s1.y) + b1s[q * 4 + 3]; h1[q * 4 + 3] = v > 0.f ? v : 0.f;
    }
#pragma unroll
    for (int q = 0; q < 4; q++) {
        float a0 = 0.f, a1 = 0.f, a2 = 0.f, a3 = 0.f;
#pragma unroll
        for (int k = 0; k < 16; k++) {
            float hv = h1[k];
            a0 += hv * W2s[k * 16 + q * 4 + 0];
            a1 += hv * W2s[k * 16 + q * 4 + 1];
            a2 += hv * W2s[k * 16 + q * 4 + 2];
            a3 += hv * W2s[k * 16 + q * 4 + 3];
        }
        ((__half2*)g_hs2h)[i * 8 + q * 2 + 0] = __float22half2_rn(make_float2(a0 * di, a1 * di));
        ((__half2*)g_hs2h)[i * 8 + q * 2 + 1] = __float22half2_rn(make_float2(a2 * di, a3 * di));
    }
}

// ---------------------------------------------------------------------------
// final: h2 = relu(dinv*(t2+hs2)+b2); GRU (h0=0 => gh=b_hh); out = h'@Wfc.T+bfc
// Also re-zeroes g_cnt for the next kernel_launch call.
// ---------------------------------------------------------------------------
__device__ __forceinline__ float sigmoidf_(float x) { return 1.0f / (1.0f + expf(-x)); }

__global__ void k_final(const float* __restrict__ b2,
                        const float* __restrict__ w_ih, const float* __restrict__ b_ih,
                        const float* __restrict__ b_hh,
                        const float* __restrict__ Wfc, const float* __restrict__ bfc,
                        float* __restrict__ out, int n) {
    __shared__ float wihs[768];
    __shared__ float wfcs[512];
    __shared__ float bihs[48];
    __shared__ float bhhs[48];
    __shared__ float bfcs[32];
    __shared__ float b2s[16];
    int t = threadIdx.x;
    for (int i = t; i < 768; i += blockDim.x) wihs[i] = w_ih[i];
    for (int i = t; i < 512; i += blockDim.x) wfcs[i] = Wfc[i];
    if (t < 48) { bihs[t] = b_ih[t]; bhhs[t] = b_hh[t]; }
    if (t < 32) bfcs[t] = bfc[t];
    if (t < 16) b2s[t] = b2[t];
    __syncthreads();

    int i = blockIdx.x * blockDim.x + threadIdx.x;
    if (i >= n) return;
    g_cnt[i] = 0;                      // reset for next call
    float di = g_dinv[i];

    float h2[16];
#pragma unroll
    for (int q = 0; q < 4; q++) {
        float4 tv = g_t2[i * 4 + q];
        float2 s0 = __half22float2(((const __half2*)g_hs2h)[i * 8 + q * 2 + 0]);
        float2 s1 = __half22float2(((const __half2*)g_hs2h)[i * 8 + q * 2 + 1]);
        float v;
        v = di * (tv.x + s0.x) + b2s[q * 4 + 0]; h2[q * 4 + 0] = v > 0.f ? v : 0.f;
        v = di * (tv.y + s0.y) + b2s[q * 4 + 1]; h2[q * 4 + 1] = v > 0.f ? v : 0.f;
        v = di * (tv.z + s1.x) + b2s[q * 4 + 2]; h2[q * 4 + 2] = v > 0.f ? v : 0.f;
        v = di * (tv.w + s1.y) + b2s[q * 4 + 3]; h2[q * 4 + 3] = v > 0.f ? v : 0.f;
    }

    float hout[16];
#pragma unroll
    for (int k = 0; k < 16; k++) {
        float ar = bihs[k], az = bihs[16 + k], an = bihs[32 + k];
#pragma unroll
        for (int c = 0; c < 16; c++) {
            float hv = h2[c];
            ar += hv * wihs[k * 16 + c];
            az += hv * wihs[(16 + k) * 16 + c];
            an += hv * wihs[(32 + k) * 16 + c];
        }
        float r = sigmoidf_(ar + bhhs[k]);
        float z = sigmoidf_(az + bhhs[16 + k]);
        float nn = tanhf(an + r * bhhs[32 + k]);
        hout[k] = (1.0f - z) * nn;
    }

    float4* outp = (float4*)(out + (size_t)i * 32);
#pragma unroll
    for (int q = 0; q < 8; q++) {
        float4 o;
        float a0 = bfcs[q * 4 + 0], a1 = bfcs[q * 4 + 1];
        float a2 = bfcs[q * 4 + 2], a3 = bfcs[q * 4 + 3];
#pragma unroll
        for (int k = 0; k < 16; k++) {
            float hv = hout[k];
            a0 += hv * wfcs[(q * 4 + 0) * 16 + k];
            a1 += hv * wfcs[(q * 4 + 1) * 16 + k];
            a2 += hv * wfcs[(q * 4 + 2) * 16 + k];
            a3 += hv * wfcs[(q * 4 + 3) * 16 + k];
        }
        o.x = a0; o.y = a1; o.z = a2; o.w = a3;
        outp[q] = o;
    }
}

// ---------------------------------------------------------------------------
extern "C" void kernel_launch(void* const* d_in, const int* in_sizes, int n_in,
                              void* d_out, int out_size) {
    const float* x    = (const float*)d_in[0];
    const int*   ei   = (const int*)  d_in[1];
    const float* W1   = (const float*)d_in[3];
    const float* b1   = (const float*)d_in[4];
    const float* W2   = (const float*)d_in[5];
    const float* b2   = (const float*)d_in[6];
    const float* w_ih = (const float*)d_in[7];
    const float* b_ih = (const float*)d_in[9];
    const float* b_hh = (const float*)d_in[10];
    const float* Wfc  = (const float*)d_in[11];
    const float* bfc  = (const float*)d_in[12];
    float* out = (float*)d_out;

    int n = in_sizes[2];           // N nodes
    int E = in_sizes[1] / 2;       // edges
    const int* src = ei;
    const int* dst = ei + E;

    int nb = (n + 1023) / 1024;    // scan blocks (<=256)

    k_count<<<(E + 255) / 256, 256>>>(dst, E);          // g_cnt starts zeroed
    k_scan1<<<nb, 256>>>(n);
    k_scan23<<<nb, 256>>>(n, nb);
    k_fill<<<(E + 255) / 256, 256>>>(src, dst, E);      // 4th launch: profiled
    k_gemm1<<<(n + 63) / 64, 128>>>(x, W1, n);

    int n8 = n * 8;
    k_gather<<<(n8 + 255) / 256, 256>>>(n, 0);
    k_combine<<<(n + 255) / 256, 256>>>(W2, b1, n);
    k_gather<<<(n8 + 255) / 256, 256>>>(n, 1);
    k_final<<<(n + 127) / 128, 128>>>(b2, w_ih, b_ih, b_hh, Wfc, bfc, out, n);
}

// round 7
// speedup vs baseline: 1.5162x; 1.0015x over previous
#include <cuda_runtime.h>
#include <cuda_fp16.h>

#define MAXN 200000
#define MAXE 6500000

// Scratch (device globals — no runtime allocation allowed)
// g_cnt is zero on first call (static init) and re-zeroed by k_final each call.
__device__ int    g_cnt[MAXN];        // in-degree (without self loop)
__device__ int    g_rowptr[MAXN];     // CSR row start
__device__ int    g_bsums[256];       // block sums for scan
__device__ int    g_csr[MAXE];        // src indices grouped by dst (compact)
__device__ unsigned g_rankpack[MAXE]; // (rank << 18) | dst  per edge
__device__ float  g_dinv[MAXN];
__device__ __half g_hs1h[MAXN * 16];  // layer-1 scaled features (fp16)
__device__ __half g_hs2h[MAXN * 16];  // layer-2 scaled features (fp16)
__device__ float4 g_t1[MAXN * 4];     // layer-1 neighbor sums (fp32)
__device__ float4 g_t2[MAXN * 4];     // layer-2 neighbor sums

// ---------------------------------------------------------------------------
// count: cnt[dst]++ per edge; the atomic's return value is this edge's rank
// within its destination bin -> packed with dst into one coalesced word.
// ---------------------------------------------------------------------------
__global__ void k_count(const int* __restrict__ dst, int E) {
    int e = blockIdx.x * blockDim.x + threadIdx.x;
    if (e >= E) return;
    int d = dst[e];
    int rank = atomicAdd(&g_cnt[d], 1);
    g_rankpack[e] = ((unsigned)rank << 18) | (unsigned)d;
}

// scan part 1: per-block (1024 elements) sums
__global__ void k_scan1(int n) {
    __shared__ int sh[256];
    int b = blockIdx.x, t = threadIdx.x;
    int i0 = b * 1024 + t * 4;
    int s = 0;
#pragma unroll
    for (int k = 0; k < 4; k++) { int i = i0 + k; if (i < n) s += g_cnt[i]; }
    sh[t] = s; __syncthreads();
    for (int off = 128; off > 0; off >>= 1) {
        if (t < off) sh[t] += sh[t + off];
        __syncthreads();
    }
    if (t == 0) g_bsums[b] = sh[0];
}

// scan part 2: every block redundantly scans block sums, then scans its chunk
__global__ void k_scan23(int n, int nb) {
    __shared__ int bs[256];
    __shared__ int sh[256];
    int b = blockIdx.x, t = threadIdx.x;

    int v = (t < nb) ? g_bsums[t] : 0;
    bs[t] = v; __syncthreads();
    for (int off = 1; off < 256; off <<= 1) {
        int a = (t >= off) ? bs[t - off] : 0;
        __syncthreads();
        bs[t] += a;
        __syncthreads();
    }
    int blockoff = (b > 0) ? bs[b - 1] : 0;

    int i0 = b * 1024 + t * 4;
    int c[4]; int s = 0;
#pragma unroll
    for (int k = 0; k < 4; k++) { int i = i0 + k; c[k] = (i < n) ? g_cnt[i] : 0; s += c[k]; }
    int tot = s;
    sh[t] = tot; __syncthreads();
    for (int off = 1; off < 256; off <<= 1) {
        int a = (t >= off) ? sh[t - off] : 0;
        __syncthreads();
        sh[t] += a;
        __syncthreads();
    }
    int run = sh[t] - tot + blockoff;
#pragma unroll
    for (int k = 0; k < 4; k++) {
        int i = i0 + k;
        if (i < n) { g_rowptr[i] = run; run += c[k]; }
    }
}

// fill: pos = rowptr[d] + rank  (NO atomics)
__global__ void k_fill(const int* __restrict__ src, int E) {
    int e = blockIdx.x * blockDim.x + threadIdx.x;
    if (e >= E) return;
    unsigned code = g_rankpack[e];
    int d = (int)(code & 0x3FFFFu);
    int rank = (int)(code >> 18);
    int pos = __ldg(g_rowptr + d) + rank;
    g_csr[pos] = src[e];
}

// ---------------------------------------------------------------------------
// GEMM1: hs1 = (x @ W1) * rsqrt(deg) -> fp16; also stores dinv.
// 128 threads, 64 nodes/block. Thread: 2 nodes x 4 channels.
// ---------------------------------------------------------------------------
__global__ void k_gemm1(const float* __restrict__ x, const float* __restrict__ W1, int n) {
    __shared__ float xs[64 * 132];
    __shared__ float Ws[128 * 16];
    int t = threadIdx.x;              // 128 threads
    int node0 = blockIdx.x * 64;

    {
        const float4* W4 = (const float4*)W1;
        float4* Wd = (float4*)Ws;
        for (int i = t; i < 512; i += 128) Wd[i] = W4[i];
    }
    {
        const float4* x4 = (const float4*)x;
        for (int i = t; i < 2048; i += 128) {
            int node = i >> 5;
            int k4 = i & 31;
            int gn = node0 + node;
            float4 v = make_float4(0.f, 0.f, 0.f, 0.f);
            if (gn < n) v = x4[(size_t)gn * 32 + k4];
            *(float4*)&xs[node * 132 + k4 * 4] = v;
        }
    }
    __syncthreads();

    int c4 = t & 3;
    int g  = t >> 2;
    int na = node0 + g * 2;
    int nb = na + 1;

    const float4* xa4 = (const float4*)(xs + (g * 2 + 0) * 132);
    const float4* xb4 = (const float4*)(xs + (g * 2 + 1) * 132);
    const float4* Ws4 = (const float4*)Ws;
    float4 A = make_float4(0.f, 0.f, 0.f, 0.f);
    float4 B = make_float4(0.f, 0.f, 0.f, 0.f);
#pragma unroll
    for (int k4 = 0; k4 < 32; k4++) {
        float4 xa = xa4[k4];
        float4 xb = xb4[k4];
        float4 w;
        w = Ws4[(4 * k4 + 0) * 4 + c4];
        A.x += xa.x * w.x; A.y += xa.x * w.y; A.z += xa.x * w.z; A.w += xa.x * w.w;
        B.x += xb.x * w.x; B.y += xb.x * w.y; B.z += xb.x * w.z; B.w += xb.x * w.w;
        w = Ws4[(4 * k4 + 1) * 4 + c4];
        A.x += xa.y * w.x; A.y += xa.y * w.y; A.z += xa.y * w.z; A.w += xa.y * w.w;
        B.x += xb.y * w.x; B.y += xb.y * w.y; B.z += xb.y * w.z; B.w += xb.y * w.w;
        w = Ws4[(4 * k4 + 2) * 4 + c4];
        A.x += xa.z * w.x; A.y += xa.z * w.y; A.z += xa.z * w.z; A.w += xa.z * w.w;
        B.x += xb.z * w.x; B.y += xb.z * w.y; B.z += xb.z * w.z; B.w += xb.z * w.w;
        w = Ws4[(4 * k4 + 3) * 4 + c4];
        A.x += xa.w * w.x; A.y += xa.w * w.y; A.z += xa.w * w.z; A.w += xa.w * w.w;
        B.x += xb.w * w.x; B.y += xb.w * w.y; B.z += xb.w * w.z; B.w += xb.w * w.w;
    }
    if (na < n) {
        float di = rsqrtf((float)g_cnt[na] + 1.0f);
        if (c4 == 0) g_dinv[na] = di;
        __half2* o = (__half2*)(g_hs1h + na * 16);
        o[c4 * 2 + 0] = __float22half2_rn(make_float2(A.x * di, A.y * di));
        o[c4 * 2 + 1] = __float22half2_rn(make_float2(A.z * di, A.w * di));
    }
    if (nb < n) {
        float di = rsqrtf((float)g_cnt[nb] + 1.0f);
        if (c4 == 0) g_dinv[nb] = di;
        __half2* o = (__half2*)(g_hs1h + nb * 16);
        o[c4 * 2 + 0] = __float22half2_rn(make_float2(B.x * di, B.y * di));
        o[c4 * 2 + 1] = __float22half2_rn(make_float2(B.z * di, B.w * di));
    }
}

// ---------------------------------------------------------------------------
// gather pass: t[i] = sum_{j in adj(i)} hs[src_j]. 8 threads per node,
// each thread owns one half2 (2 channels). Batched 8-deep for MLP.
// ---------------------------------------------------------------------------
__global__ void k_gather(int n, int layer) {
    int gid = blockIdx.x * blockDim.x + threadIdx.x;
    int node = gid >> 3;
    int sub  = gid & 7;
    if (node >= n) return;
    const unsigned* hs = (const unsigned*)(layer ? g_hs2h : g_hs1h);
    float2* tt = (float2*)(layer ? g_t2 : g_t1);

    int row = g_rowptr[node];
    int cnt = g_cnt[node];
    const int* cs = g_csr + row;

    float ax = 0.f, ay = 0.f;
    int j = 0;
    for (; j + 8 <= cnt; j += 8) {
        int s[8];
#pragma unroll
        for (int q = 0; q < 8; q++) s[q] = __ldg(cs + j + q);
        unsigned u[8];
#pragma unroll
        for (int q = 0; q < 8; q++) u[q] = __ldg(hs + s[q] * 8 + sub);
#pragma unroll
        for (int q = 0; q < 8; q++) {
            float2 f = __half22float2(*(const __half2*)&u[q]);
            ax += f.x; ay += f.y;
        }
    }
    for (; j < cnt; j++) {
        int s = __ldg(cs + j);
        unsigned u = __ldg(hs + s * 8 + sub);
        float2 f = __half22float2(*(const __half2*)&u);
        ax += f.x; ay += f.y;
    }
    tt[node * 8 + sub] = make_float2(ax, ay);
}

// ---------------------------------------------------------------------------
// combine: h1 = relu(dinv*(t1+hs1)+b1); hs2 = (h1 @ W2)*dinv -> fp16.
// ---------------------------------------------------------------------------
__global__ void k_combine(const float* __restrict__ W2, const float* __restrict__ b1, int n) {
    __shared__ float W2s[256];
    __shared__ float b1s[16];
    int t = threadIdx.x;
    if (t < 256) W2s[t] = W2[t];
    if (t < 16)  b1s[t] = b1[t];
    __syncthreads();

    int i = blockIdx.x * blockDim.x + threadIdx.x;
    if (i >= n) return;
    float di = g_dinv[i];

    float h1[16];
#pragma unroll
    for (int q = 0; q < 4; q++) {
        float4 tv = g_t1[i * 4 + q];
        float2 s0 = __half22float2(((const __half2*)g_hs1h)[i * 8 + q * 2 + 0]);
        float2 s1 = __half22float2(((const __half2*)g_hs1h)[i * 8 + q * 2 + 1]);
        float v;
        v = di * (tv.x + s0.x) + b1s[q * 4 + 0]; h1[q * 4 + 0] = v > 0.f ? v : 0.f;
        v = di * (tv.y + s0.y) + b1s[q * 4 + 1]; h1[q * 4 + 1] = v > 0.f ? v : 0.f;
        v = di * (tv.z + s1.x) + b1s[q * 4 + 2]; h1[q * 4 + 2] = v > 0.f ? v : 0.f;
        v = di * (tv.w + s1.y) + b1s[q * 4 + 3]; h1[q * 4 + 3] = v > 0.f ? v : 0.f;
    }
#pragma unroll
    for (int q = 0; q < 4; q++) {
        float a0 = 0.f, a1 = 0.f, a2 = 0.f, a3 = 0.f;
#pragma unroll
        for (int k = 0; k < 16; k++) {
            float hv = h1[k];
            a0 += hv * W2s[k * 16 + q * 4 + 0];
            a1 += hv * W2s[k * 16 + q * 4 + 1];
            a2 += hv * W2s[k * 16 + q * 4 + 2];
            a3 += hv * W2s[k * 16 + q * 4 + 3];
        }
        ((__half2*)g_hs2h)[i * 8 + q * 2 + 0] = __float22half2_rn(make_float2(a0 * di, a1 * di));
        ((__half2*)g_hs2h)[i * 8 + q * 2 + 1] = __float22half2_rn(make_float2(a2 * di, a3 * di));
    }
}

// ---------------------------------------------------------------------------
// final: h2 = relu(dinv*(t2+hs2)+b2); GRU (h0=0 => gh=b_hh); out = h'@Wfc.T+bfc
// Also re-zeroes g_cnt for the next kernel_launch call.
// ---------------------------------------------------------------------------
__device__ __forceinline__ float sigmoidf_(float x) { return 1.0f / (1.0f + expf(-x)); }

__global__ void k_final(const float* __restrict__ b2,
                        const float* __restrict__ w_ih, const float* __restrict__ b_ih,
                        const float* __restrict__ b_hh,
                        const float* __restrict__ Wfc, const float* __restrict__ bfc,
                        float* __restrict__ out, int n) {
    __shared__ float wihs[768];
    __shared__ float wfcs[512];
    __shared__ float bihs[48];
    __shared__ float bhhs[48];
    __shared__ float bfcs[32];
    __shared__ float b2s[16];
    int t = threadIdx.x;
    for (int i = t; i < 768; i += blockDim.x) wihs[i] = w_ih[i];
    for (int i = t; i < 512; i += blockDim.x) wfcs[i] = Wfc[i];
    if (t < 48) { bihs[t] = b_ih[t]; bhhs[t] = b_hh[t]; }
    if (t < 32) bfcs[t] = bfc[t];
    if (t < 16) b2s[t] = b2[t];
    __syncthreads();

    int i = blockIdx.x * blockDim.x + threadIdx.x;
    if (i >= n) return;
    g_cnt[i] = 0;                      // reset for next call
    float di = g_dinv[i];

    float h2[16];
#pragma unroll
    for (int q = 0; q < 4; q++) {
        float4 tv = g_t2[i * 4 + q];
        float2 s0 = __half22float2(((const __half2*)g_hs2h)[i * 8 + q * 2 + 0]);
        float2 s1 = __half22float2(((const __half2*)g_hs2h)[i * 8 + q * 2 + 1]);
        float v;
        v = di * (tv.x + s0.x) + b2s[q * 4 + 0]; h2[q * 4 + 0] = v > 0.f ? v : 0.f;
        v = di * (tv.y + s0.y) + b2s[q * 4 + 1]; h2[q * 4 + 1] = v > 0.f ? v : 0.f;
        v = di * (tv.z + s1.x) + b2s[q * 4 + 2]; h2[q * 4 + 2] = v > 0.f ? v : 0.f;
        v = di * (tv.w + s1.y) + b2s[q * 4 + 3]; h2[q * 4 + 3] = v > 0.f ? v : 0.f;
    }

    float hout[16];
#pragma unroll
    for (int k = 0; k < 16; k++) {
        float ar = bihs[k], az = bihs[16 + k], an = bihs[32 + k];
#pragma unroll
        for (int c = 0; c < 16; c++) {
            float hv = h2[c];
            ar += hv * wihs[k * 16 + c];
            az += hv * wihs[(16 + k) * 16 + c];
            an += hv * wihs[(32 + k) * 16 + c];
        }
        float r = sigmoidf_(ar + bhhs[k]);
        float z = sigmoidf_(az + bhhs[16 + k]);
        float nn = tanhf(an + r * bhhs[32 + k]);
        hout[k] = (1.0f - z) * nn;
    }

    float4* outp = (float4*)(out + (size_t)i * 32);
#pragma unroll
    for (int q = 0; q < 8; q++) {
        float4 o;
        float a0 = bfcs[q * 4 + 0], a1 = bfcs[q * 4 + 1];
        float a2 = bfcs[q * 4 + 2], a3 = bfcs[q * 4 + 3];
#pragma unroll
        for (int k = 0; k < 16; k++) {
            float hv = hout[k];
            a0 += hv * wfcs[(q * 4 + 0) * 16 + k];
            a1 += hv * wfcs[(q * 4 + 1) * 16 + k];
            a2 += hv * wfcs[(q * 4 + 2) * 16 + k];
            a3 += hv * wfcs[(q * 4 + 3) * 16 + k];
        }
        o.x = a0; o.y = a1; o.z = a2; o.w = a3;
        outp[q] = o;
    }
}

// ---------------------------------------------------------------------------
extern "C" void kernel_launch(void* const* d_in, const int* in_sizes, int n_in,
                              void* d_out, int out_size) {
    const float* x    = (const float*)d_in[0];
    const int*   ei   = (const int*)  d_in[1];
    const float* W1   = (const float*)d_in[3];
    const float* b1   = (const float*)d_in[4];
    const float* W2   = (const float*)d_in[5];
    const float* b2   = (const float*)d_in[6];
    const float* w_ih = (const float*)d_in[7];
    const float* b_ih = (const float*)d_in[9];
    const float* b_hh = (const float*)d_in[10];
    const float* Wfc  = (const float*)d_in[11];
    const float* bfc  = (const float*)d_in[12];
    float* out = (float*)d_out;

    int n = in_sizes[2];           // N nodes
    int E = in_sizes[1] / 2;       // edges
    const int* src = ei;
    const int* dst = ei + E;

    int nb = (n + 1023) / 1024;    // scan blocks (<=256)

    k_count<<<(E + 255) / 256, 256>>>(dst, E);          // g_cnt starts zeroed
    k_scan1<<<nb, 256>>>(n);
    k_scan23<<<nb, 256>>>(n, nb);
    k_fill<<<(E + 255) / 256, 256>>>(src, E);           // 4th launch: profiled
    k_gemm1<<<(n + 63) / 64, 128>>>(x, W1, n);

    int n8 = n * 8;
    k_gather<<<(n8 + 255) / 256, 256>>>(n, 0);
    k_combine<<<(n + 255) / 256, 256>>>(W2, b1, n);
    k_gather<<<(n8 + 255) / 256, 256>>>(n, 1);
    k_final<<<(n + 127) / 128, 128>>>(b2, w_ih, b_ih, b_hh, Wfc, bfc, out, n);
}